// round 14
// baseline (speedup 1.0000x reference)
#include <cuda_runtime.h>
#include <cuda_bf16.h>

#define SB 2048
#define BB 32
#define DD 512
#define HH 512
#define G4 2048
#define MTOT (SB*BB)

// ---- device scratch (static __device__ globals; no allocations) ----
__device__ float    g_gx[(size_t)MTOT * G4];   // layer-0 input projections
__device__ unsigned g_h0[4][BB * HH];          // layer-0 h, 4-deep ring, packed hi16|lo16
__device__ unsigned g_h1[2][BB * HH];          // layer-1 h, double-buffered, packed
__device__ unsigned g_leaf[8 * 128];           // flag leaves: [0-3]=cntL0 [4-7]=cntL1done

static __device__ __forceinline__ void split_bf16(float v, unsigned short& hi, unsigned short& lo) {
    __nv_bfloat16 h = __float2bfloat16_rn(v);
    float r = v - __bfloat162float(h);
    hi = __bfloat16_as_ushort(h);
    lo = __bfloat16_as_ushort(__float2bfloat16_rn(r));
}

static __device__ __forceinline__ void mma16816(float* d, const unsigned* a, const unsigned* b) {
    asm volatile(
        "mma.sync.aligned.m16n8k16.row.col.f32.bf16.bf16.f32 "
        "{%0,%1,%2,%3}, {%4,%5,%6,%7}, {%8,%9}, {%0,%1,%2,%3};\n"
        : "+f"(d[0]), "+f"(d[1]), "+f"(d[2]), "+f"(d[3])
        : "r"(a[0]), "r"(a[1]), "r"(a[2]), "r"(a[3]), "r"(b[0]), "r"(b[1]));
}

static __device__ __forceinline__ float sigf(float x) { return 1.0f / (1.0f + expf(-x)); }

// poll two 4-leaf banks until bank0 >= t0 and bankX >= t1 on every leaf (tid0 only)
static __device__ __forceinline__ void poll_flags(const unsigned* bank0, const unsigned* bankX,
                                                  unsigned t0, unsigned t1) {
    bool done = false;
    while (!done) {
        unsigned a0, a1, a2, a3, b0, b1, b2, b3;
        asm volatile("ld.relaxed.gpu.global.u32 %0, [%1];" : "=r"(a0) : "l"(bank0 + 0 * 128) : "memory");
        asm volatile("ld.relaxed.gpu.global.u32 %0, [%1];" : "=r"(a1) : "l"(bank0 + 1 * 128) : "memory");
        asm volatile("ld.relaxed.gpu.global.u32 %0, [%1];" : "=r"(a2) : "l"(bank0 + 2 * 128) : "memory");
        asm volatile("ld.relaxed.gpu.global.u32 %0, [%1];" : "=r"(a3) : "l"(bank0 + 3 * 128) : "memory");
        asm volatile("ld.relaxed.gpu.global.u32 %0, [%1];" : "=r"(b0) : "l"(bankX + 0 * 128) : "memory");
        asm volatile("ld.relaxed.gpu.global.u32 %0, [%1];" : "=r"(b1) : "l"(bankX + 1 * 128) : "memory");
        asm volatile("ld.relaxed.gpu.global.u32 %0, [%1];" : "=r"(b2) : "l"(bankX + 2 * 128) : "memory");
        asm volatile("ld.relaxed.gpu.global.u32 %0, [%1];" : "=r"(b3) : "l"(bankX + 3 * 128) : "memory");
        done = (a0 >= t0) & (a1 >= t0) & (a2 >= t0) & (a3 >= t0)
             & (b0 >= t1) & (b1 >= t1) & (b2 >= t1) & (b3 >= t1);
    }
    asm volatile("fence.acq_rel.gpu;" ::: "memory");
}

// ============================================================================
// Layer-0 input projection GEMM: gx[m][n] = X_row(m).Wih0[n] + bias, m = s*32+b
// ============================================================================
__global__ void __launch_bounds__(256) gx_gemm(const float* __restrict__ Xf,
                                               const float* __restrict__ W,
                                               const float* __restrict__ bia,
                                               const float* __restrict__ bib) {
    __shared__ __align__(16) unsigned short sAhi[128][36], sAlo[128][36];
    __shared__ __align__(16) unsigned short sBhi[64][36],  sBlo[64][36];
    __shared__ float sBias[64];

    const int tid = threadIdx.x;
    const int n0 = blockIdx.x * 64, m0 = blockIdx.y * 128;
    if (tid < 64) sBias[tid] = bia[n0 + tid] + bib[n0 + tid];

    const int w = tid >> 5, lane = tid & 31;
    const int wm = w >> 1, wn = w & 1;

    float C[2][4][4];
#pragma unroll
    for (int i = 0; i < 2; i++)
#pragma unroll
        for (int j = 0; j < 4; j++)
#pragma unroll
            for (int k = 0; k < 4; k++) C[i][j][k] = 0.f;

    const int rg = tid >> 3, kq = (tid & 7) * 4;

    for (int kc = 0; kc < 16; kc++) {
        const int k0 = kc * 32;
#pragma unroll
        for (int rr = 0; rr < 4; rr++) {
            const int r = rg + rr * 32, m = m0 + r;
            const int b = m & 31, s = m >> 5;
            const float4 f = *reinterpret_cast<const float4*>(Xf + ((size_t)(b * SB + s)) * DD + k0 + kq);
            const float v[4] = {f.x, f.y, f.z, f.w};
#pragma unroll
            for (int j = 0; j < 4; j++) {
                unsigned short hi, lo; split_bf16(v[j], hi, lo);
                sAhi[r][kq + j] = hi; sAlo[r][kq + j] = lo;
            }
        }
#pragma unroll
        for (int rr = 0; rr < 2; rr++) {
            const int r = rg + rr * 32;
            const float4 f = *reinterpret_cast<const float4*>(W + (size_t)(n0 + r) * DD + k0 + kq);
            const float v[4] = {f.x, f.y, f.z, f.w};
#pragma unroll
            for (int j = 0; j < 4; j++) {
                unsigned short hi, lo; split_bf16(v[j], hi, lo);
                sBhi[r][kq + j] = hi; sBlo[r][kq + j] = lo;
            }
        }
        __syncthreads();

#pragma unroll
        for (int ks = 0; ks < 2; ks++) {
            const int kk = ks * 16 + (lane & 3) * 2;
            unsigned Ah[2][4], Al[2][4], Bh[4][2], Bl[4][2];
#pragma unroll
            for (int mt = 0; mt < 2; mt++) {
                const int r = wm * 32 + mt * 16 + (lane >> 2);
                Ah[mt][0] = *(const unsigned*)&sAhi[r][kk];
                Ah[mt][1] = *(const unsigned*)&sAhi[r + 8][kk];
                Ah[mt][2] = *(const unsigned*)&sAhi[r][kk + 8];
                Ah[mt][3] = *(const unsigned*)&sAhi[r + 8][kk + 8];
                Al[mt][0] = *(const unsigned*)&sAlo[r][kk];
                Al[mt][1] = *(const unsigned*)&sAlo[r + 8][kk];
                Al[mt][2] = *(const unsigned*)&sAlo[r][kk + 8];
                Al[mt][3] = *(const unsigned*)&sAlo[r + 8][kk + 8];
            }
#pragma unroll
            for (int nt = 0; nt < 4; nt++) {
                const int n = wn * 32 + nt * 8 + (lane >> 2);
                Bh[nt][0] = *(const unsigned*)&sBhi[n][kk];
                Bh[nt][1] = *(const unsigned*)&sBhi[n][kk + 8];
                Bl[nt][0] = *(const unsigned*)&sBlo[n][kk];
                Bl[nt][1] = *(const unsigned*)&sBlo[n][kk + 8];
            }
#pragma unroll
            for (int mt = 0; mt < 2; mt++)
#pragma unroll
                for (int nt = 0; nt < 4; nt++) {
                    mma16816(C[mt][nt], Ah[mt], Bh[nt]);
                    mma16816(C[mt][nt], Ah[mt], Bl[nt]);
                    mma16816(C[mt][nt], Al[mt], Bh[nt]);
                }
        }
        __syncthreads();
    }

#pragma unroll
    for (int mt = 0; mt < 2; mt++)
#pragma unroll
        for (int nt = 0; nt < 4; nt++) {
            const int r  = m0 + wm * 32 + mt * 16 + (lane >> 2);
            const int cn = wn * 32 + nt * 8 + (lane & 3) * 2;
            const float b0v = sBias[cn], b1v = sBias[cn + 1];
            *reinterpret_cast<float2*>(g_gx + (size_t)r * G4 + n0 + cn) =
                make_float2(C[mt][nt][0] + b0v, C[mt][nt][1] + b1v);
            *reinterpret_cast<float2*>(g_gx + (size_t)(r + 8) * G4 + n0 + cn) =
                make_float2(C[mt][nt][2] + b0v, C[mt][nt][3] + b1v);
        }
}

__global__ void zero_bar() {
    if (threadIdx.x < 8) g_leaf[threadIdx.x * 128] = 0;
}

// ============================================================================
// Fused 2-layer pipelined recurrence, NO SMEM h staging: fragments built
// directly from L2 (pipelined __ldcg + PRMT). h0 = 4-deep ring -> L0's WAR
// gate is L1done(r-2); "staged" counter deleted.
// Blocks 0-63 = layer 0 (t=r); blocks 64-127 = layer 1 (t=r-1).
// FIX vs round 12: A-fragment loads now include the per-warp K-slice offset
// (ws*KSL for L0; (ws&3)*128 within the selected h0/h1 source for L1).
// ============================================================================
template <int LAY>
static __device__ __forceinline__ void run_layer(
    const float* __restrict__ Wa,   // LAY0: Whh0 ; LAY1: Wih1
    const float* __restrict__ Wb,   // LAY1: Whh1
    const float* __restrict__ bi, const float* __restrict__ bh,
    float* __restrict__ dout, float* sP)
{
    const int tid = threadIdx.x;
    const int ug = blockIdx.x & 63, u0 = ug * 8;
    const int ws = tid >> 5, lane = tid & 31;
    const int lf = (int)(blockIdx.x & 3);
    constexpr int KSL = LAY ? 128 : 64;   // k-range per warp
    constexpr int NKS = KSL / 16;         // 8 (L1) or 4 (L0)

    // ---- preload register-resident split-bf16 weight fragments (all 4 gates) ----
    unsigned Bhi[NKS][4][2], Blo[NKS][4][2];
#pragma unroll
    for (int gg = 0; gg < 4; gg++) {
        const int row = gg * 512 + u0 + (lane >> 2);
        const float* wr;
        if (LAY == 0) wr = Wa + (size_t)row * HH + ws * KSL;
        else          wr = (ws < 4) ? (Wa + (size_t)row * HH + ws * 128)
                                    : (Wb + (size_t)row * HH + (ws - 4) * 128);
#pragma unroll
        for (int ks = 0; ks < NKS; ks++) {
            const int k = ks * 16 + (lane & 3) * 2;
            unsigned short h0, l0, h1, l1;
            split_bf16(wr[k], h0, l0);     split_bf16(wr[k + 1], h1, l1);
            Bhi[ks][gg][0] = (unsigned)h0 | ((unsigned)h1 << 16);
            Blo[ks][gg][0] = (unsigned)l0 | ((unsigned)l1 << 16);
            split_bf16(wr[k + 8], h0, l0); split_bf16(wr[k + 9], h1, l1);
            Bhi[ks][gg][1] = (unsigned)h0 | ((unsigned)h1 << 16);
            Blo[ks][gg][1] = (unsigned)l0 | ((unsigned)l1 << 16);
        }
    }

    float cst = 0.f;
    const int bl = tid >> 3, ul = tid & 7;   // (batch, unit) for elementwise

    float pg[4];
    if (LAY == 0) {   // prefetch gx for t=0
        const float* gp = g_gx + (size_t)bl * G4 + u0 + ul;
        pg[0] = __ldcs(gp);        pg[1] = __ldcs(gp + 512);
        pg[2] = __ldcs(gp + 1024); pg[3] = __ldcs(gp + 1536);
    } else {          // constant bias
        pg[0] = bi[u0 + ul]        + bh[u0 + ul];
        pg[1] = bi[512 + u0 + ul]  + bh[512 + u0 + ul];
        pg[2] = bi[1024 + u0 + ul] + bh[1024 + u0 + ul];
        pg[3] = bi[1536 + u0 + ul] + bh[1536 + u0 + ul];
    }

    // L1 initial wait: L0 must finish round 0 before L1 round 1 reads h0[0]
    if (LAY == 1) {
        if (tid == 0) poll_flags(g_leaf, g_leaf + 4 * 128, 16u, 0u);
        __syncthreads();
    }

    const int rbeg = LAY ? 1 : 0;
    const int rend = LAY ? SB : SB - 1;   // inclusive

    const int r0 = lane >> 2, kq = (lane & 3) * 2;
    // per-warp K-slice base offset within its A source (THE round-12 fix)
    const int koff = (LAY == 0) ? (ws * KSL) : ((ws & 3) * 128);

    for (int r = rbeg; r <= rend; r++) {
        const int t = LAY ? (r - 1) : r;

        // ---- per-warp A source in global memory (packed h) ----
        const unsigned* asrc = nullptr;
        if (LAY == 0) {
            if (t > 0) asrc = g_h0[(t - 1) & 3];
        } else {
            if (ws < 4) asrc = g_h0[t & 3];
            else if (t > 0) asrc = g_h1[(t - 1) & 1];
        }

        if (asrc) {
            // ---- MMA with direct-from-L2 pipelined fragment loads ----
            float C[2][4][4];
#pragma unroll
            for (int i = 0; i < 2; i++)
#pragma unroll
                for (int j = 0; j < 4; j++)
#pragma unroll
                    for (int k = 0; k < 4; k++) C[i][j][k] = 0.f;

            const unsigned* abase = asrc + koff + kq;
            uint2 buf[2][8];
            {   // load ks=0
                const int kk = 0;
#pragma unroll
                for (int mt = 0; mt < 2; mt++) {
                    const int m = mt * 16 + r0;
                    buf[0][mt * 4 + 0] = __ldcg((const uint2*)(abase + m * HH + kk));
                    buf[0][mt * 4 + 1] = __ldcg((const uint2*)(abase + (m + 8) * HH + kk));
                    buf[0][mt * 4 + 2] = __ldcg((const uint2*)(abase + m * HH + kk + 8));
                    buf[0][mt * 4 + 3] = __ldcg((const uint2*)(abase + (m + 8) * HH + kk + 8));
                }
            }
#pragma unroll
            for (int ks = 0; ks < NKS; ks++) {
                if (ks + 1 < NKS) {
                    const int kk = (ks + 1) * 16;
                    uint2* nb = buf[(ks + 1) & 1];
#pragma unroll
                    for (int mt = 0; mt < 2; mt++) {
                        const int m = mt * 16 + r0;
                        nb[mt * 4 + 0] = __ldcg((const uint2*)(abase + m * HH + kk));
                        nb[mt * 4 + 1] = __ldcg((const uint2*)(abase + (m + 8) * HH + kk));
                        nb[mt * 4 + 2] = __ldcg((const uint2*)(abase + m * HH + kk + 8));
                        nb[mt * 4 + 3] = __ldcg((const uint2*)(abase + (m + 8) * HH + kk + 8));
                    }
                }
                const uint2* b = buf[ks & 1];
                unsigned ah[2][4], al[2][4];
#pragma unroll
                for (int mt = 0; mt < 2; mt++)
#pragma unroll
                    for (int j = 0; j < 4; j++) {
                        ah[mt][j] = __byte_perm(b[mt * 4 + j].x, b[mt * 4 + j].y, 0x7632);
                        al[mt][j] = __byte_perm(b[mt * 4 + j].x, b[mt * 4 + j].y, 0x5410);
                    }
#pragma unroll
                for (int mt = 0; mt < 2; mt++)
#pragma unroll
                    for (int gg = 0; gg < 4; gg++) {
                        mma16816(C[mt][gg], ah[mt], Bhi[ks][gg]);
                        mma16816(C[mt][gg], ah[mt], Blo[ks][gg]);
                        mma16816(C[mt][gg], al[mt], Bhi[ks][gg]);
                    }
            }
            // publish partials: sP[ws][gate][batch 32][unit 8]
            const int cc = (lane & 3) * 2;
#pragma unroll
            for (int mt = 0; mt < 2; mt++)
#pragma unroll
                for (int gg = 0; gg < 4; gg++) {
                    float* base = sP + (size_t)((ws * 4 + gg) * 32) * 8;
                    const int m = mt * 16 + r0;
                    base[m * 8 + cc]           = C[mt][gg][0];
                    base[m * 8 + cc + 1]       = C[mt][gg][1];
                    base[(m + 8) * 8 + cc]     = C[mt][gg][2];
                    base[(m + 8) * 8 + cc + 1] = C[mt][gg][3];
                }
        } else {
            // inactive source (t==0 zeros): zero this warp's partial blocks
            float* basew = sP + (size_t)(ws * 4) * 256;
            for (int i = lane; i < 1024; i += 32) basew[i] = 0.f;
        }
        __syncthreads();

        // ---- LSTM elementwise: sum 8 K-slice partials per gate ----
        {
            float gv4[4];
#pragma unroll
            for (int gg = 0; gg < 4; gg++) {
                float s = pg[gg];
#pragma unroll
                for (int wsl = 0; wsl < 8; wsl++)
                    s += sP[(size_t)((wsl * 4 + gg) * 32 + bl) * 8 + ul];
                gv4[gg] = s;
            }
            cst = sigf(gv4[1]) * cst + sigf(gv4[0]) * tanhf(gv4[2]);
            const float h = sigf(gv4[3]) * tanhf(cst);
            unsigned short hh, hl; split_bf16(h, hh, hl);
            const unsigned hp = ((unsigned)hh << 16) | (unsigned)hl;
            if (LAY == 0) {
                __stcg(&g_h0[t & 3][bl * HH + u0 + ul], hp);
                if (t + 1 < SB) {   // prefetch next gx during flag wait
                    const float* gp = g_gx + ((size_t)(t + 1) * BB + bl) * G4 + u0 + ul;
                    pg[0] = __ldcs(gp);        pg[1] = __ldcs(gp + 512);
                    pg[2] = __ldcs(gp + 1024); pg[3] = __ldcs(gp + 1536);
                }
            } else {
                __stcg(&g_h1[t & 1][bl * HH + u0 + ul], hp);
                __stcs(&dout[((size_t)bl * SB + t) * HH + u0 + ul], h);
            }
        }
        __syncthreads();

        // ---- arrive (release own h stores + consumed reads) + wait deps ----
        if (tid == 0) {
            asm volatile("red.release.gpu.global.add.u32 [%0], 1;"
                         :: "l"(&g_leaf[((LAY ? 4 : 0) + lf) * 128]) : "memory");
            if (r < rend) {
                unsigned t0 = 16u * (unsigned)(r + 1);  // cntL0: all L0 done round r (next reads need it)
                unsigned t1;
                if (LAY == 0) t1 = (r >= 2) ? 16u * (unsigned)(r - 2) : 0u;  // L1done(r-2): h0 ring WAR
                else          t1 = 16u * (unsigned)r;                        // L1done(r): h1 RAW/WAR
                poll_flags(g_leaf, g_leaf + 4 * 128, t0, t1);
            }
        }
        __syncthreads();
    }
}

__global__ void __launch_bounds__(256, 1) lstm_fused(
    const float* __restrict__ Whh0, const float* __restrict__ Wih1,
    const float* __restrict__ Whh1,
    const float* __restrict__ bi1,  const float* __restrict__ bh1,
    float* __restrict__ dout)
{
    extern __shared__ float sP[];
    if (blockIdx.x < 64) run_layer<0>(Whh0, Whh0, Whh0, Whh0, dout, sP);
    else                 run_layer<1>(Wih1, Whh1, bi1, bh1, dout, sP);
}

extern "C" void kernel_launch(void* const* d_in, const int* in_sizes, int n_in,
                              void* d_out, int out_size) {
    const float* X   = (const float*)d_in[0];
    const float* Wih = (const float*)d_in[1];
    const float* Whh = (const float*)d_in[2];
    const float* bih = (const float*)d_in[3];
    const float* bhh = (const float*)d_in[4];
    float* out = (float*)d_out;

    const int smem_bytes = 8 * 4 * 32 * 8 * 4;  // sP: 32 KB
    cudaFuncSetAttribute(lstm_fused, cudaFuncAttributeMaxDynamicSharedMemorySize, smem_bytes);

    dim3 gg(32, 512);
    gx_gemm<<<gg, 256>>>(X, Wih, bih, bhh);        // layer-0 input projections
    zero_bar<<<1, 32>>>();
    lstm_fused<<<128, 256, smem_bytes>>>(Whh,                      // Whh0
                                         Wih + (size_t)G4 * DD,    // Wih1
                                         Whh + (size_t)G4 * HH,    // Whh1
                                         bih + G4, bhh + G4, out);
}